// round 15
// baseline (speedup 1.0000x reference)
#include <cuda_runtime.h>
#include <cuda_fp16.h>
#include <math.h>
#include <stdint.h>

// ---------------------------------------------------------------------------
// Problem constants
// ---------------------------------------------------------------------------
#define BATCH 8
#define CCH   384
#define HH    56
#define WW    56
#define HWSZ  (HH*WW)         // 3136
#define NTOK  (BATCH*HWSZ)    // 25088
#define QKVC  (3*CCH)         // 1152
#define HIDN  1536
#define NHEAD 12
#define HDIM  32
#define EPSLN 1e-5f

// ---------------------------------------------------------------------------
// Scratch
// ---------------------------------------------------------------------------
__device__ __half g_xn [(size_t)NTOK*CCH];
__device__ float  g_xpT[(size_t)NTOK*CCH];
__device__ __half g_qkv[(size_t)NTOK*QKVC];
__device__ __half g_att[(size_t)NTOK*CCH];
__device__ float  g_xpb[(size_t)NTOK*CCH];
__device__ __half g_x2 [(size_t)NTOK*CCH];
__device__ __half g_h  [(size_t)NTOK*HIDN];
__device__ __half g_wq[(size_t)QKVC*CCH];
__device__ __half g_wp[(size_t)CCH*CCH];
__device__ __half g_w1[(size_t)HIDN*CCH];
__device__ __half g_w2[(size_t)CCH*HIDN];

// ---------------------------------------------------------------------------
// helpers
// ---------------------------------------------------------------------------
__device__ __forceinline__ uint32_t smem_u32(const void* p) {
    uint32_t a;
    asm("{ .reg .u64 t; cvta.to.shared.u64 t, %1; cvt.u32.u64 %0, t; }"
        : "=r"(a) : "l"(p));
    return a;
}
__device__ __forceinline__ void cp_async16(uint32_t s, const void* g) {
    asm volatile("cp.async.cg.shared.global [%0], [%1], 16;"
                 :: "r"(s), "l"(g));
}
__device__ __forceinline__ void cp_commit() {
    asm volatile("cp.async.commit_group;" ::: "memory");
}
template<int N>
__device__ __forceinline__ void cp_wait() {
    asm volatile("cp.async.wait_group %0;" :: "n"(N) : "memory");
}
__device__ __forceinline__ void ldmatrix_x4(uint32_t& r0, uint32_t& r1,
                                            uint32_t& r2, uint32_t& r3,
                                            uint32_t addr) {
    asm volatile("ldmatrix.sync.aligned.m8n8.x4.shared.b16 {%0,%1,%2,%3}, [%4];"
                 : "=r"(r0), "=r"(r1), "=r"(r2), "=r"(r3) : "r"(addr));
}
__device__ __forceinline__ void mma_f16(float* c, const uint32_t* a,
                                        const uint32_t* b) {
    asm volatile(
        "mma.sync.aligned.m16n8k16.row.col.f32.f16.f16.f32 "
        "{%0,%1,%2,%3}, {%4,%5,%6,%7}, {%8,%9}, {%0,%1,%2,%3};"
        : "+f"(c[0]), "+f"(c[1]), "+f"(c[2]), "+f"(c[3])
        : "r"(a[0]), "r"(a[1]), "r"(a[2]), "r"(a[3]),
          "r"(b[0]), "r"(b[1]));
}

// ---------------------------------------------------------------------------
// Fused weight convert fp32 -> half (all 4 weights in one launch)
// ---------------------------------------------------------------------------
#define WN1 (QKVC*CCH)
#define WN2 (CCH*CCH)
#define WN3 (HIDN*CCH)
#define WN4 (CCH*HIDN)
#define WNT (WN1+WN2+WN3+WN4)

__global__ __launch_bounds__(256) void convw4_kernel(
    const float* __restrict__ s1, const float* __restrict__ s2,
    const float* __restrict__ s3, const float* __restrict__ s4,
    __half* __restrict__ d1, __half* __restrict__ d2,
    __half* __restrict__ d3, __half* __restrict__ d4)
{
    int i = blockIdx.x * 256 + threadIdx.x;
    if (i < WN1) { d1[i] = __float2half(s1[i]); return; }
    i -= WN1;
    if (i < WN2) { d2[i] = __float2half(s2[i]); return; }
    i -= WN2;
    if (i < WN3) { d3[i] = __float2half(s3[i]); return; }
    i -= WN3;
    if (i < WN4) d4[i] = __float2half(s4[i]);
}

// ---------------------------------------------------------------------------
// fp16 mma.sync GEMM:  C[M,Nc] = A[M,K] @ Bw[Nc,K]^T
// CTA tile 128x128, BK=64 halves (128B rows, XOR swizzle), 3-stage cp.async.
// 128 threads = 4 warps as 2(M)x2(N); warp tile 64x64 via m16n8k16 + ldmatrix.
// 2 CTAs/SM (96KB smem): independent barrier scopes + epilogue/mainloop
// overlap across CTAs; 64x64 warp tile = 1.5x less smem-read per FLOP.
// mode: 0 = plain -> half out
//       1 = bias + exact erf GELU -> half out
//       2 = bias + fp32 residual -> float out [N,C]
//       3 = bias + fp32 residual -> float out [B,C,HW] (fused transpose)
// ---------------------------------------------------------------------------
#define OPST   16384                 // bytes per operand tile (128 x 128B)
#define NSTAGE 3
#define GEMM_SMEM (NSTAGE*2*OPST)    // 98304

__global__ __launch_bounds__(128, 2) void gemm_f16_kernel(
    const __half* __restrict__ A, const __half* __restrict__ Bw,
    const float* __restrict__ bias, const float* __restrict__ resid,
    void* __restrict__ Cout, int M, int Nc, int K, int mode)
{
    extern __shared__ char smem[];
    uint32_t sb = smem_u32(smem);

    int tid    = threadIdx.x;
    int wid    = tid >> 5;
    int lane   = tid & 31;
    int warp_m = wid & 1;            // 0..1 -> 64-row halves
    int warp_n = wid >> 1;           // 0..1 -> 64-col halves
    int m0     = blockIdx.x * 128;
    int n0     = blockIdx.y * 128;

    const __half* Ab = A  + (size_t)m0 * K;
    const __half* Bb = Bw + (size_t)n0 * K;
    const int NCH = K >> 6;

    int gid = lane >> 2;
    int tig = lane & 3;

    int arow_l = (lane & 7) + ((lane >> 3) & 1) * 8;
    int asub   = (lane >> 4) & 1;
    int brow_l = (lane & 7) + ((lane >> 4) & 1) * 8;
    int bsub   = (lane >> 3) & 1;

    float acc[4][8][4];
    #pragma unroll
    for (int i = 0; i < 4; i++)
        #pragma unroll
        for (int j = 0; j < 8; j++)
            #pragma unroll
            for (int q = 0; q < 4; q++) acc[i][j][q] = 0.f;

    // A: 1024 granules + B: 1024 granules over 128 threads -> 16 each
    auto load_chunk = [&](int kc, int st) {
        uint32_t abase = sb + st * (2*OPST);
        uint32_t bbase = abase + OPST;
        int kh = kc << 6;
        #pragma unroll
        for (int r = 0; r < 16; r++) {
            int idx = tid + r * 128;          // 0..2047
            int op  = idx >> 10;              // 0=A, 1=B
            int wi  = idx & 1023;
            int row = wi >> 3;
            int g   = wi & 7;
            uint32_t dst = (op ? bbase : abase)
                         + (uint32_t)(row * 128 + ((g ^ (row & 7)) << 4));
            const __half* src = (op ? Bb : Ab) + (size_t)row * K + kh + g * 8;
            cp_async16(dst, src);
        }
        cp_commit();
    };

    load_chunk(0, 0);
    load_chunk(1, 1);

    for (int i = 0; i < NCH; i++) {
        if (i < NCH - 1) cp_wait<1>(); else cp_wait<0>();
        __syncthreads();

        int st = i % NSTAGE;
        uint32_t abase = sb + st * (2*OPST);
        uint32_t bbase = abase + OPST;

        #pragma unroll
        for (int ks = 0; ks < 4; ks++) {
            uint32_t afr[4][4];
            #pragma unroll
            for (int mf = 0; mf < 4; mf++) {
                int row = warp_m * 64 + mf * 16 + arow_l;
                int gph = ((ks * 2 + asub) ^ (row & 7));
                ldmatrix_x4(afr[mf][0], afr[mf][1], afr[mf][2], afr[mf][3],
                            abase + (uint32_t)(row * 128 + gph * 16));
            }
            uint32_t bfr[8][2];
            #pragma unroll
            for (int pf = 0; pf < 4; pf++) {
                int row = warp_n * 64 + pf * 16 + brow_l;
                int gph = ((ks * 2 + bsub) ^ (row & 7));
                ldmatrix_x4(bfr[2*pf][0], bfr[2*pf][1],
                            bfr[2*pf+1][0], bfr[2*pf+1][1],
                            bbase + (uint32_t)(row * 128 + gph * 16));
            }
            #pragma unroll
            for (int mf = 0; mf < 4; mf++)
                #pragma unroll
                for (int nf = 0; nf < 8; nf++)
                    mma_f16(acc[mf][nf], afr[mf], bfr[nf]);
        }

        if (i + 2 < NCH) load_chunk(i + 2, (i + 2) % NSTAGE);
    }

    // ---------------- epilogue ----------------
    if (mode == 3) {
        // bias + residual, stage 128x128 tile in smem, write [B,C,HW]
        __syncthreads();
        float* tile = (float*)smem;            // [128][129] = 66048B
        #pragma unroll
        for (int mf = 0; mf < 4; mf++) {
            #pragma unroll
            for (int nf = 0; nf < 8; nf++) {
                int rl = warp_m * 64 + mf * 16 + gid;
                int cl = warp_n * 64 + nf * 8 + tig * 2;
                #pragma unroll
                for (int half_i = 0; half_i < 2; half_i++) {
                    int r = rl + half_i * 8;
                    size_t rr = (size_t)(m0 + r);
                    float v0 = acc[mf][nf][half_i * 2 + 0] + bias[n0 + cl];
                    float v1 = acc[mf][nf][half_i * 2 + 1] + bias[n0 + cl + 1];
                    float2 rv = *(const float2*)&resid[rr * Nc + n0 + cl];
                    v0 += rv.x; v1 += rv.y;
                    tile[r * 129 + cl    ] = v0;
                    tile[r * 129 + cl + 1] = v1;
                }
            }
        }
        __syncthreads();
        float* out = (float*)Cout;
        #pragma unroll
        for (int cs = 0; cs < 32; cs++) {
            int c = wid * 32 + cs;
            #pragma unroll
            for (int rs = 0; rs < 4; rs++) {
                int r  = rs * 32 + lane;
                int rr = m0 + r;
                int b  = rr / HWSZ;
                int s  = rr - b * HWSZ;
                out[((size_t)b * CCH + n0 + c) * HWSZ + s] = tile[r * 129 + c];
            }
        }
        return;
    }

    #pragma unroll
    for (int mf = 0; mf < 4; mf++) {
        #pragma unroll
        for (int nf = 0; nf < 8; nf++) {
            int row = m0 + warp_m * 64 + mf * 16 + gid;
            int col = n0 + warp_n * 64 + nf * 8 + tig * 2;
            #pragma unroll
            for (int half_i = 0; half_i < 2; half_i++) {
                size_t rr = (size_t)(row + half_i * 8);
                float v0 = acc[mf][nf][half_i * 2 + 0];
                float v1 = acc[mf][nf][half_i * 2 + 1];
                if (bias) { v0 += bias[col]; v1 += bias[col + 1]; }
                if (mode == 1) {
                    v0 = 0.5f * v0 * (1.0f + erff(v0 * 0.7071067811865476f));
                    v1 = 0.5f * v1 * (1.0f + erff(v1 * 0.7071067811865476f));
                }
                if (mode == 2) {
                    float2 rv = *(const float2*)&resid[rr * Nc + col];
                    v0 += rv.x; v1 += rv.y;
                    float2 o; o.x = v0; o.y = v1;
                    *(float2*)&((float*)Cout)[rr * Nc + col] = o;
                } else {
                    __half2 o = __floats2half2_rn(v0, v1);
                    *(__half2*)&((__half*)Cout)[rr * Nc + col] = o;
                }
            }
        }
    }
}

// ---------------------------------------------------------------------------
// LN1: x [B,C,H,W] -> xn [N,C] (half) + xpT [N,C] (fp32)
// ---------------------------------------------------------------------------
__global__ __launch_bounds__(256) void ln1_kernel(
    const float* __restrict__ x, const float* __restrict__ gam,
    const float* __restrict__ bet, __half* __restrict__ xn,
    float* __restrict__ xpT)
{
    const int TPB = 28;
    __shared__ float s[CCH*TPB];
    __shared__ float ps[9*TPB];
    __shared__ float pq[9*TPB];
    __shared__ float s_mean[TPB];
    __shared__ float s_rstd[TPB];

    int tid = threadIdx.x;
    int x0  = blockIdx.x * TPB;
    int y   = blockIdx.y;
    int b   = blockIdx.z;

    for (int idx = tid; idx < CCH*TPB; idx += 256) {
        int c = idx / TPB;
        int t = idx % TPB;
        s[idx] = x[(((size_t)b*CCH + c)*HH + y)*WW + x0 + t];
    }
    __syncthreads();

    if (tid < 9*TPB) {
        int sub = tid / TPB;
        int t   = tid % TPB;
        float sm = 0.f, sq = 0.f;
        for (int c = sub; c < CCH; c += 9) {
            float v = s[c*TPB + t];
            sm += v; sq += v*v;
        }
        ps[sub*TPB + t] = sm;
        pq[sub*TPB + t] = sq;
    }
    __syncthreads();
    if (tid < TPB) {
        float sm = 0.f, sq = 0.f;
        #pragma unroll
        for (int sub = 0; sub < 9; sub++) { sm += ps[sub*TPB + tid]; sq += pq[sub*TPB + tid]; }
        float mu  = sm * (1.f/CCH);
        float var = sq * (1.f/CCH) - mu*mu;
        s_mean[tid] = mu;
        s_rstd[tid] = rsqrtf(var + EPSLN);
    }
    __syncthreads();

    for (int idx = tid; idx < CCH*TPB; idx += 256) {
        int t = idx / CCH;
        int c = idx % CCH;
        float v = s[c*TPB + t];
        size_t n = (size_t)b*HWSZ + (size_t)y*WW + (x0 + t);
        xpT[n*CCH + c] = v;
        xn [n*CCH + c] =
            __float2half((v - s_mean[t]) * s_rstd[t] * gam[c] + bet[c]);
    }
}

// ---------------------------------------------------------------------------
// Multi-dilation 3x3 local attention + fused "+xn" residual.
// One warp = one head x FOUR adjacent tokens (4p..4p+3 along W; WW%4==0 so
// groups never cross rows). 8 lanes per token, 4 dims (2 x half2) per lane.
// Butterfly offsets 4,2,1 stay inside each 8-lane group. 32-bit addressing;
// neighbor deltas warp-uniform. OOB -> logit 0, v 0 (zero-pad unfold).
// ---------------------------------------------------------------------------
__global__ __launch_bounds__(384) void attn_kernel(
    const __half* __restrict__ qkv, const __half* __restrict__ xn,
    __half* __restrict__ att)
{
    int n    = blockIdx.x * 4 + ((threadIdx.x >> 3) & 3);
    int w    = threadIdx.x >> 5;      // head 0..11
    int l8   = threadIdx.x & 7;       // 4-dim group index

    int b    = n / HWSZ;
    int rem  = n - b * HWSZ;
    int y    = rem / WW;
    int xx   = rem - y * WW;

    int dil  = (w >> 2) + 1;          // DILS = (1,2,3)
    int c0   = w * HDIM;

    const float scale = 0.17677669529663687f;   // 32^-0.5

    uint32_t base = (uint32_t)n * QKVC + c0 + 4 * l8;

    __half2 qa = ((const __half2*)(qkv + base))[0];
    __half2 qb = ((const __half2*)(qkv + base))[1];
    float2 qfa = __half22float2(qa);
    float2 qfb = __half22float2(qb);

    float    logit[9];
    int      delta[9];
    unsigned okm = 0;
    #pragma unroll
    for (int e = 0; e < 9; e++) {
        int ki = e / 3, kj = e % 3;
        int ny = y  + (ki - 1) * dil;
        int nx = xx + (kj - 1) * dil;
        bool ok = ((unsigned)ny < HH) && ((unsigned)nx < WW);
        delta[e] = ((ki - 1) * WW + (kj - 1)) * dil * QKVC;
        float p = 0.f;
        if (ok) {
            okm |= (1u << e);
            const __half2* kp = (const __half2*)(qkv + (int)base + CCH + delta[e]);
            float2 ka = __half22float2(kp[0]);
            float2 kb = __half22float2(kp[1]);
            p = qfa.x * ka.x + qfa.y * ka.y + qfb.x * kb.x + qfb.y * kb.y;
        }
        #pragma unroll
        for (int off = 4; off > 0; off >>= 1)
            p += __shfl_xor_sync(0xffffffffu, p, off);
        logit[e] = p * scale;
    }

    float mx = logit[0];
    #pragma unroll
    for (int e = 1; e < 9; e++) mx = fmaxf(mx, logit[e]);
    float pe[9];
    float sum = 0.f;
    #pragma unroll
    for (int e = 0; e < 9; e++) { pe[e] = __expf(logit[e] - mx); sum += pe[e]; }
    float inv = 1.f / sum;

    float oxa = 0.f, oya = 0.f, oxb = 0.f, oyb = 0.f;
    #pragma unroll
    for (int e = 0; e < 9; e++) {
        if (okm & (1u << e)) {
            const __half2* vp = (const __half2*)(qkv + (int)base + 2*CCH + delta[e]);
            float2 va = __half22float2(vp[0]);
            float2 vb = __half22float2(vp[1]);
            float p = pe[e] * inv;
            oxa = fmaf(p, va.x, oxa);
            oya = fmaf(p, va.y, oya);
            oxb = fmaf(p, vb.x, oxb);
            oyb = fmaf(p, vb.y, oyb);
        }
    }

    uint32_t obase = (uint32_t)n * CCH + c0 + 4 * l8;
    __half2* op = (__half2*)(att + obase);
    const __half2* xp = (const __half2*)(xn + obase);
    float2 xa = __half22float2(xp[0]);
    float2 xb = __half22float2(xp[1]);
    op[0] = __floats2half2_rn(oxa + xa.x, oya + xa.y);
    op[1] = __floats2half2_rn(oxb + xb.x, oyb + xb.y);
}

// ---------------------------------------------------------------------------
// LN2: fp32 in -> half out
// ---------------------------------------------------------------------------
__global__ __launch_bounds__(128) void ln2_kernel(
    const float* __restrict__ in, const float* __restrict__ gam,
    const float* __restrict__ bet, __half* __restrict__ out)
{
    __shared__ float rs[4], rq[4];
    __shared__ float s_mu, s_rstd;
    int n   = blockIdx.x;
    int tid = threadIdx.x;
    const float* row = in + (size_t)n * CCH;

    float v0 = row[tid];
    float v1 = row[tid + 128];
    float v2 = row[tid + 256];
    float sm = v0 + v1 + v2;
    float sq = v0*v0 + v1*v1 + v2*v2;
    #pragma unroll
    for (int off = 16; off > 0; off >>= 1) {
        sm += __shfl_xor_sync(0xffffffffu, sm, off);
        sq += __shfl_xor_sync(0xffffffffu, sq, off);
    }
    int wid = tid >> 5, lane = tid & 31;
    if (lane == 0) { rs[wid] = sm; rq[wid] = sq; }
    __syncthreads();
    if (tid == 0) {
        float tsm = rs[0]+rs[1]+rs[2]+rs[3];
        float tsq = rq[0]+rq[1]+rq[2]+rq[3];
        float mu  = tsm * (1.f/CCH);
        float var = tsq * (1.f/CCH) - mu*mu;
        s_mu = mu;
        s_rstd = rsqrtf(var + EPSLN);
    }
    __syncthreads();
    float mu = s_mu, rstd = s_rstd;
    __half* orow = out + (size_t)n * CCH;
    orow[tid      ] = __float2half((v0 - mu) * rstd * gam[tid      ] + bet[tid      ]);
    orow[tid + 128] = __float2half((v1 - mu) * rstd * gam[tid + 128] + bet[tid + 128]);
    orow[tid + 256] = __float2half((v2 - mu) * rstd * gam[tid + 256] + bet[tid + 256]);
}

// ---------------------------------------------------------------------------
// kernel_launch
// ---------------------------------------------------------------------------
extern "C" void kernel_launch(void* const* d_in, const int* in_sizes, int n_in,
                              void* d_out, int out_size)
{
    const float* x      = (const float*)d_in[0];
    const float* qkv_w  = (const float*)d_in[1];
    const float* proj_w = (const float*)d_in[2];
    const float* proj_b = (const float*)d_in[3];
    const float* n1_g   = (const float*)d_in[4];
    const float* n1_b   = (const float*)d_in[5];
    const float* n2_g   = (const float*)d_in[6];
    const float* n2_b   = (const float*)d_in[7];
    const float* fc1_w  = (const float*)d_in[8];
    const float* fc1_b  = (const float*)d_in[9];
    const float* fc2_w  = (const float*)d_in[10];
    const float* fc2_b  = (const float*)d_in[11];
    float* out = (float*)d_out;

    __half *xn, *qkv, *att, *x2, *h, *wq, *wp, *w1, *w2;
    float *xpT, *xpb;
    cudaGetSymbolAddress((void**)&xn,  g_xn);
    cudaGetSymbolAddress((void**)&xpT, g_xpT);
    cudaGetSymbolAddress((void**)&qkv, g_qkv);
    cudaGetSymbolAddress((void**)&att, g_att);
    cudaGetSymbolAddress((void**)&xpb, g_xpb);
    cudaGetSymbolAddress((void**)&x2,  g_x2);
    cudaGetSymbolAddress((void**)&h,   g_h);
    cudaGetSymbolAddress((void**)&wq,  g_wq);
    cudaGetSymbolAddress((void**)&wp,  g_wp);
    cudaGetSymbolAddress((void**)&w1,  g_w1);
    cudaGetSymbolAddress((void**)&w2,  g_w2);

    cudaFuncSetAttribute(gemm_f16_kernel,
                         cudaFuncAttributeMaxDynamicSharedMemorySize, GEMM_SMEM);

    // 0. convert all weights to half (single launch)
    convw4_kernel<<<(WNT + 255)/256, 256>>>(qkv_w, proj_w, fc1_w, fc2_w,
                                            wq, wp, w1, w2);

    // 1. LN1 + NCHW->NHWC transpose
    ln1_kernel<<<dim3(2, HH, BATCH), 256>>>(x, n1_g, n1_b, xn, xpT);

    // 2. QKV: [N,384] @ [1152,384]^T -> half
    gemm_f16_kernel<<<dim3(NTOK/128, QKVC/128), 128, GEMM_SMEM>>>(
        xn, wq, nullptr, nullptr, qkv, NTOK, QKVC, CCH, 0);

    // 3. attention + xn residual -> half (4 tokens per warp)
    attn_kernel<<<NTOK/4, 384>>>(qkv, xn, att);

    // 4. proj + bias + residual(xpT) -> fp32 [N,C]
    gemm_f16_kernel<<<dim3(NTOK/128, CCH/128), 128, GEMM_SMEM>>>(
        att, wp, proj_b, xpT, xpb, NTOK, CCH, CCH, 2);

    // 5. LN2 -> half
    ln2_kernel<<<NTOK, 128>>>(xpb, n2_g, n2_b, x2);

    // 6. fc1 + bias + exact GELU -> half
    gemm_f16_kernel<<<dim3(NTOK/128, HIDN/128), 128, GEMM_SMEM>>>(
        x2, w1, fc1_b, nullptr, h, NTOK, HIDN, CCH, 1);

    // 7. fc2 + bias + residual(xpb) -> fp32 [B,C,HW] (fused transpose)
    gemm_f16_kernel<<<dim3(NTOK/128, CCH/128), 128, GEMM_SMEM>>>(
        h, w2, fc2_b, xpb, out, NTOK, CCH, HIDN, 3);
}

// round 16
// speedup vs baseline: 1.0040x; 1.0040x over previous
#include <cuda_runtime.h>
#include <cuda_fp16.h>
#include <math.h>
#include <stdint.h>

// ---------------------------------------------------------------------------
// Problem constants
// ---------------------------------------------------------------------------
#define BATCH 8
#define CCH   384
#define HH    56
#define WW    56
#define HWSZ  (HH*WW)         // 3136
#define NTOK  (BATCH*HWSZ)    // 25088
#define QKVC  (3*CCH)         // 1152
#define HIDN  1536
#define NHEAD 12
#define HDIM  32
#define EPSLN 1e-5f

// ---------------------------------------------------------------------------
// Scratch
// ---------------------------------------------------------------------------
__device__ __half g_xn [(size_t)NTOK*CCH];
__device__ float  g_xpT[(size_t)NTOK*CCH];
__device__ __half g_qkv[(size_t)NTOK*QKVC];
__device__ __half g_att[(size_t)NTOK*CCH];
__device__ float  g_xpb[(size_t)NTOK*CCH];
__device__ __half g_x2 [(size_t)NTOK*CCH];
__device__ __half g_h  [(size_t)NTOK*HIDN];
__device__ __half g_wq[(size_t)QKVC*CCH];
__device__ __half g_wp[(size_t)CCH*CCH];
__device__ __half g_w1[(size_t)HIDN*CCH];
__device__ __half g_w2[(size_t)CCH*HIDN];

// ---------------------------------------------------------------------------
// helpers
// ---------------------------------------------------------------------------
__device__ __forceinline__ uint32_t smem_u32(const void* p) {
    uint32_t a;
    asm("{ .reg .u64 t; cvta.to.shared.u64 t, %1; cvt.u32.u64 %0, t; }"
        : "=r"(a) : "l"(p));
    return a;
}
__device__ __forceinline__ void cp_async16(uint32_t s, const void* g) {
    asm volatile("cp.async.cg.shared.global [%0], [%1], 16;"
                 :: "r"(s), "l"(g));
}
__device__ __forceinline__ void cp_commit() {
    asm volatile("cp.async.commit_group;" ::: "memory");
}
template<int N>
__device__ __forceinline__ void cp_wait() {
    asm volatile("cp.async.wait_group %0;" :: "n"(N) : "memory");
}
__device__ __forceinline__ void ldmatrix_x4(uint32_t& r0, uint32_t& r1,
                                            uint32_t& r2, uint32_t& r3,
                                            uint32_t addr) {
    asm volatile("ldmatrix.sync.aligned.m8n8.x4.shared.b16 {%0,%1,%2,%3}, [%4];"
                 : "=r"(r0), "=r"(r1), "=r"(r2), "=r"(r3) : "r"(addr));
}
__device__ __forceinline__ void mma_f16(float* c, const uint32_t* a,
                                        const uint32_t* b) {
    asm volatile(
        "mma.sync.aligned.m16n8k16.row.col.f32.f16.f16.f32 "
        "{%0,%1,%2,%3}, {%4,%5,%6,%7}, {%8,%9}, {%0,%1,%2,%3};"
        : "+f"(c[0]), "+f"(c[1]), "+f"(c[2]), "+f"(c[3])
        : "r"(a[0]), "r"(a[1]), "r"(a[2]), "r"(a[3]),
          "r"(b[0]), "r"(b[1]));
}

// ---------------------------------------------------------------------------
// Fused weight convert fp32 -> half (all 4 weights in one launch)
// ---------------------------------------------------------------------------
#define WN1 (QKVC*CCH)
#define WN2 (CCH*CCH)
#define WN3 (HIDN*CCH)
#define WN4 (CCH*HIDN)
#define WNT (WN1+WN2+WN3+WN4)

__global__ __launch_bounds__(256) void convw4_kernel(
    const float* __restrict__ s1, const float* __restrict__ s2,
    const float* __restrict__ s3, const float* __restrict__ s4,
    __half* __restrict__ d1, __half* __restrict__ d2,
    __half* __restrict__ d3, __half* __restrict__ d4)
{
    int i = blockIdx.x * 256 + threadIdx.x;
    if (i < WN1) { d1[i] = __float2half(s1[i]); return; }
    i -= WN1;
    if (i < WN2) { d2[i] = __float2half(s2[i]); return; }
    i -= WN2;
    if (i < WN3) { d3[i] = __float2half(s3[i]); return; }
    i -= WN3;
    if (i < WN4) d4[i] = __float2half(s4[i]);
}

// ---------------------------------------------------------------------------
// fp16 mma.sync GEMM (round-12 best config):  C[M,Nc] = A[M,K] @ Bw[Nc,K]^T
// CTA tile 128x128, BK=64 halves (128B rows, XOR swizzle), 3-stage cp.async.
// 256 threads = 8 warps as 2(M)x4(N); warp tile 64x32 via m16n8k16 + ldmatrix.
// 2 CTAs/SM (96KB smem) -> 16 warps/SM.
// mode: 0 = plain -> half out
//       1 = bias + exact erf GELU -> half out
//       2 = bias + fp32 residual -> float out [N,C]
//       3 = bias + fp32 residual -> float out [B,C,HW] (fused transpose)
// ---------------------------------------------------------------------------
#define OPST   16384
#define NSTAGE 3
#define GEMM_SMEM (NSTAGE*2*OPST)    // 98304

__global__ __launch_bounds__(256, 2) void gemm_f16_kernel(
    const __half* __restrict__ A, const __half* __restrict__ Bw,
    const float* __restrict__ bias, const float* __restrict__ resid,
    void* __restrict__ Cout, int M, int Nc, int K, int mode)
{
    extern __shared__ char smem[];
    uint32_t sb = smem_u32(smem);

    int tid    = threadIdx.x;
    int wid    = tid >> 5;
    int lane   = tid & 31;
    int warp_m = wid & 1;
    int warp_n = wid >> 1;
    int m0     = blockIdx.x * 128;
    int n0     = blockIdx.y * 128;

    const __half* Ab = A  + (size_t)m0 * K;
    const __half* Bb = Bw + (size_t)n0 * K;
    const int NCH = K >> 6;

    int gid = lane >> 2;
    int tig = lane & 3;

    int arow_l = (lane & 7) + ((lane >> 3) & 1) * 8;
    int asub   = (lane >> 4) & 1;
    int brow_l = (lane & 7) + ((lane >> 4) & 1) * 8;
    int bsub   = (lane >> 3) & 1;

    float acc[4][4][4];
    #pragma unroll
    for (int i = 0; i < 4; i++)
        #pragma unroll
        for (int j = 0; j < 4; j++)
            #pragma unroll
            for (int q = 0; q < 4; q++) acc[i][j][q] = 0.f;

    auto load_chunk = [&](int kc, int st) {
        uint32_t abase = sb + st * (2*OPST);
        uint32_t bbase = abase + OPST;
        int kh = kc << 6;
        #pragma unroll
        for (int r = 0; r < 8; r++) {
            int idx = tid + r * 256;
            int op  = idx >> 10;
            int wi  = idx & 1023;
            int row = wi >> 3;
            int g   = wi & 7;
            uint32_t dst = (op ? bbase : abase)
                         + (uint32_t)(row * 128 + ((g ^ (row & 7)) << 4));
            const __half* src = (op ? Bb : Ab) + (size_t)row * K + kh + g * 8;
            cp_async16(dst, src);
        }
        cp_commit();
    };

    load_chunk(0, 0);
    load_chunk(1, 1);

    for (int i = 0; i < NCH; i++) {
        if (i < NCH - 1) cp_wait<1>(); else cp_wait<0>();
        __syncthreads();

        int st = i % NSTAGE;
        uint32_t abase = sb + st * (2*OPST);
        uint32_t bbase = abase + OPST;

        #pragma unroll
        for (int ks = 0; ks < 4; ks++) {
            uint32_t afr[4][4];
            #pragma unroll
            for (int mf = 0; mf < 4; mf++) {
                int row = warp_m * 64 + mf * 16 + arow_l;
                int gph = ((ks * 2 + asub) ^ (row & 7));
                ldmatrix_x4(afr[mf][0], afr[mf][1], afr[mf][2], afr[mf][3],
                            abase + (uint32_t)(row * 128 + gph * 16));
            }
            uint32_t bfr[4][2];
            #pragma unroll
            for (int pf = 0; pf < 2; pf++) {
                int row = warp_n * 32 + pf * 16 + brow_l;
                int gph = ((ks * 2 + bsub) ^ (row & 7));
                ldmatrix_x4(bfr[2*pf][0], bfr[2*pf][1],
                            bfr[2*pf+1][0], bfr[2*pf+1][1],
                            bbase + (uint32_t)(row * 128 + gph * 16));
            }
            #pragma unroll
            for (int mf = 0; mf < 4; mf++)
                #pragma unroll
                for (int nf = 0; nf < 4; nf++)
                    mma_f16(acc[mf][nf], afr[mf], bfr[nf]);
        }

        if (i + 2 < NCH) load_chunk(i + 2, (i + 2) % NSTAGE);
    }

    // ---------------- epilogue ----------------
    if (mode == 3) {
        __syncthreads();
        float* tile = (float*)smem;            // [128][129]
        #pragma unroll
        for (int mf = 0; mf < 4; mf++) {
            #pragma unroll
            for (int nf = 0; nf < 4; nf++) {
                int rl = warp_m * 64 + mf * 16 + gid;
                int cl = warp_n * 32 + nf * 8 + tig * 2;
                #pragma unroll
                for (int half_i = 0; half_i < 2; half_i++) {
                    int r = rl + half_i * 8;
                    size_t rr = (size_t)(m0 + r);
                    float v0 = acc[mf][nf][half_i * 2 + 0] + bias[n0 + cl];
                    float v1 = acc[mf][nf][half_i * 2 + 1] + bias[n0 + cl + 1];
                    float2 rv = *(const float2*)&resid[rr * Nc + n0 + cl];
                    v0 += rv.x; v1 += rv.y;
                    tile[r * 129 + cl    ] = v0;
                    tile[r * 129 + cl + 1] = v1;
                }
            }
        }
        __syncthreads();
        float* out = (float*)Cout;
        #pragma unroll
        for (int cs = 0; cs < 16; cs++) {
            int c = wid * 16 + cs;
            #pragma unroll
            for (int rs = 0; rs < 4; rs++) {
                int r  = rs * 32 + lane;
                int rr = m0 + r;
                int b  = rr / HWSZ;
                int s  = rr - b * HWSZ;
                out[((size_t)b * CCH + n0 + c) * HWSZ + s] = tile[r * 129 + c];
            }
        }
        return;
    }

    #pragma unroll
    for (int mf = 0; mf < 4; mf++) {
        #pragma unroll
        for (int nf = 0; nf < 4; nf++) {
            int row = m0 + warp_m * 64 + mf * 16 + gid;
            int col = n0 + warp_n * 32 + nf * 8 + tig * 2;
            #pragma unroll
            for (int half_i = 0; half_i < 2; half_i++) {
                size_t rr = (size_t)(row + half_i * 8);
                float v0 = acc[mf][nf][half_i * 2 + 0];
                float v1 = acc[mf][nf][half_i * 2 + 1];
                if (bias) { v0 += bias[col]; v1 += bias[col + 1]; }
                if (mode == 1) {
                    v0 = 0.5f * v0 * (1.0f + erff(v0 * 0.7071067811865476f));
                    v1 = 0.5f * v1 * (1.0f + erff(v1 * 0.7071067811865476f));
                }
                if (mode == 2) {
                    float2 rv = *(const float2*)&resid[rr * Nc + col];
                    v0 += rv.x; v1 += rv.y;
                    float2 o; o.x = v0; o.y = v1;
                    *(float2*)&((float*)Cout)[rr * Nc + col] = o;
                } else {
                    __half2 o = __floats2half2_rn(v0, v1);
                    *(__half2*)&((__half*)Cout)[rr * Nc + col] = o;
                }
            }
        }
    }
}

// ---------------------------------------------------------------------------
// LN1: x [B,C,H,W] -> xn [N,C] (half) + xpT [N,C] (fp32)
// ---------------------------------------------------------------------------
__global__ __launch_bounds__(256) void ln1_kernel(
    const float* __restrict__ x, const float* __restrict__ gam,
    const float* __restrict__ bet, __half* __restrict__ xn,
    float* __restrict__ xpT)
{
    const int TPB = 28;
    __shared__ float s[CCH*TPB];
    __shared__ float ps[9*TPB];
    __shared__ float pq[9*TPB];
    __shared__ float s_mean[TPB];
    __shared__ float s_rstd[TPB];

    int tid = threadIdx.x;
    int x0  = blockIdx.x * TPB;
    int y   = blockIdx.y;
    int b   = blockIdx.z;

    for (int idx = tid; idx < CCH*TPB; idx += 256) {
        int c = idx / TPB;
        int t = idx % TPB;
        s[idx] = x[(((size_t)b*CCH + c)*HH + y)*WW + x0 + t];
    }
    __syncthreads();

    if (tid < 9*TPB) {
        int sub = tid / TPB;
        int t   = tid % TPB;
        float sm = 0.f, sq = 0.f;
        for (int c = sub; c < CCH; c += 9) {
            float v = s[c*TPB + t];
            sm += v; sq += v*v;
        }
        ps[sub*TPB + t] = sm;
        pq[sub*TPB + t] = sq;
    }
    __syncthreads();
    if (tid < TPB) {
        float sm = 0.f, sq = 0.f;
        #pragma unroll
        for (int sub = 0; sub < 9; sub++) { sm += ps[sub*TPB + tid]; sq += pq[sub*TPB + tid]; }
        float mu  = sm * (1.f/CCH);
        float var = sq * (1.f/CCH) - mu*mu;
        s_mean[tid] = mu;
        s_rstd[tid] = rsqrtf(var + EPSLN);
    }
    __syncthreads();

    for (int idx = tid; idx < CCH*TPB; idx += 256) {
        int t = idx / CCH;
        int c = idx % CCH;
        float v = s[c*TPB + t];
        size_t n = (size_t)b*HWSZ + (size_t)y*WW + (x0 + t);
        xpT[n*CCH + c] = v;
        xn [n*CCH + c] =
            __float2half((v - s_mean[t]) * s_rstd[t] * gam[c] + bet[c]);
    }
}

// ---------------------------------------------------------------------------
// Row-strip multi-dilation attention + fused "+xn" residual.
// One block per (row y, branch, batch). Stages the 3 K rows + 3 V rows of
// this branch (128 ch x 56 cols each) into smem once; computes 56 tokens x
// 4 heads against smem. All gmem/smem warp accesses are contiguous 256B.
// Warp = one token x 4 heads (8 lanes x 4 dims each); butterfly 4/2/1 within
// 8-lane head groups. OOB rows/cols never loaded and never read (okm mask),
// contributing exactly logit 0 / v 0 (zero-pad unfold semantics).
// ---------------------------------------------------------------------------
#define ATT_ROW   (56*128)                 // halves per row-slice
#define ATT_SMEM  (2*3*ATT_ROW*2)          // K + V = 86016 bytes

__global__ __launch_bounds__(256) void attn_kernel(
    const __half* __restrict__ qkv, const __half* __restrict__ xn,
    __half* __restrict__ att)
{
    extern __shared__ char smem[];
    __half* ks = (__half*)smem;            // [3][56][128]
    __half* vs = ks + 3*ATT_ROW;

    int y   = blockIdx.x;
    int br  = blockIdx.y;                  // 0..2
    int b   = blockIdx.z;
    int dil = br + 1;
    int c0  = br * 128;
    int tid = threadIdx.x;

    // ---- stage K/V rows (skip OOB rows; they are never read) ----
    #pragma unroll
    for (int r = 0; r < 3; r++) {
        int ny = y + (r - 1) * dil;
        if ((unsigned)ny >= HH) continue;
        const __half* srcK = qkv + (size_t)(b*HWSZ + ny*WW) * QKVC + CCH + c0;
        const __half* srcV = srcK + CCH;
        __half* dstK = ks + r * ATT_ROW;
        __half* dstV = vs + r * ATT_ROW;
        for (int g = tid; g < 56*16; g += 256) {
            int col = g >> 4;
            int gr  = g & 15;
            *(int4*)(dstK + col*128 + gr*8) =
                *(const int4*)(srcK + (size_t)col*QKVC + gr*8);
            *(int4*)(dstV + col*128 + gr*8) =
                *(const int4*)(srcV + (size_t)col*QKVC + gr*8);
        }
    }
    __syncthreads();

    int wid  = tid >> 5;
    int lane = tid & 31;
    int hh   = lane >> 3;                  // head-in-branch 0..3
    int l8   = lane & 7;                   // 4-dim group

    const float scale = 0.17677669529663687f;   // 32^-0.5
    int chq = c0 + hh*32 + l8*4;

    #pragma unroll
    for (int it = 0; it < 7; it++) {
        int col = wid * 7 + it;            // token col 0..55
        int n   = b*HWSZ + y*WW + col;

        uint32_t qoff = (uint32_t)n * QKVC + chq;
        float2 qfa = __half22float2(*(const __half2*)(qkv + qoff));
        float2 qfb = __half22float2(*(const __half2*)(qkv + qoff + 2));

        float    logit[9];
        int      soff[9];
        unsigned okm = 0;
        #pragma unroll
        for (int e = 0; e < 9; e++) {
            int ki = e / 3, kj = e % 3;
            int ny = y   + (ki - 1) * dil;
            int nx = col + (kj - 1) * dil;
            bool ok = ((unsigned)ny < HH) && ((unsigned)nx < WW);
            soff[e] = (ki*56 + nx)*128 + hh*32 + l8*4;
            float p = 0.f;
            if (ok) {
                okm |= (1u << e);
                float2 ka = __half22float2(*(const __half2*)(ks + soff[e]));
                float2 kb = __half22float2(*(const __half2*)(ks + soff[e] + 2));
                p = qfa.x*ka.x + qfa.y*ka.y + qfb.x*kb.x + qfb.y*kb.y;
            }
            #pragma unroll
            for (int off = 4; off > 0; off >>= 1)
                p += __shfl_xor_sync(0xffffffffu, p, off);
            logit[e] = p * scale;
        }

        float mx = logit[0];
        #pragma unroll
        for (int e = 1; e < 9; e++) mx = fmaxf(mx, logit[e]);
        float pe[9];
        float sum = 0.f;
        #pragma unroll
        for (int e = 0; e < 9; e++) { pe[e] = __expf(logit[e] - mx); sum += pe[e]; }
        float inv = 1.f / sum;

        float oxa = 0.f, oya = 0.f, oxb = 0.f, oyb = 0.f;
        #pragma unroll
        for (int e = 0; e < 9; e++) {
            if (okm & (1u << e)) {
                float2 va = __half22float2(*(const __half2*)(vs + soff[e]));
                float2 vb = __half22float2(*(const __half2*)(vs + soff[e] + 2));
                float p = pe[e] * inv;
                oxa = fmaf(p, va.x, oxa);
                oya = fmaf(p, va.y, oya);
                oxb = fmaf(p, vb.x, oxb);
                oyb = fmaf(p, vb.y, oyb);
            }
        }

        uint32_t obase = (uint32_t)n * CCH + chq;
        const __half2* xp = (const __half2*)(xn + obase);
        float2 xa = __half22float2(xp[0]);
        float2 xb = __half22float2(xp[1]);
        __half2* op = (__half2*)(att + obase);
        op[0] = __floats2half2_rn(oxa + xa.x, oya + xa.y);
        op[1] = __floats2half2_rn(oxb + xb.x, oyb + xb.y);
    }
}

// ---------------------------------------------------------------------------
// LN2: fp32 in -> half out
// ---------------------------------------------------------------------------
__global__ __launch_bounds__(128) void ln2_kernel(
    const float* __restrict__ in, const float* __restrict__ gam,
    const float* __restrict__ bet, __half* __restrict__ out)
{
    __shared__ float rs[4], rq[4];
    __shared__ float s_mu, s_rstd;
    int n   = blockIdx.x;
    int tid = threadIdx.x;
    const float* row = in + (size_t)n * CCH;

    float v0 = row[tid];
    float v1 = row[tid + 128];
    float v2 = row[tid + 256];
    float sm = v0 + v1 + v2;
    float sq = v0*v0 + v1*v1 + v2*v2;
    #pragma unroll
    for (int off = 16; off > 0; off >>= 1) {
        sm += __shfl_xor_sync(0xffffffffu, sm, off);
        sq += __shfl_xor_sync(0xffffffffu, sq, off);
    }
    int wid = tid >> 5, lane = tid & 31;
    if (lane == 0) { rs[wid] = sm; rq[wid] = sq; }
    __syncthreads();
    if (tid == 0) {
        float tsm = rs[0]+rs[1]+rs[2]+rs[3];
        float tsq = rq[0]+rq[1]+rq[2]+rq[3];
        float mu  = tsm * (1.f/CCH);
        float var = tsq * (1.f/CCH) - mu*mu;
        s_mu = mu;
        s_rstd = rsqrtf(var + EPSLN);
    }
    __syncthreads();
    float mu = s_mu, rstd = s_rstd;
    __half* orow = out + (size_t)n * CCH;
    orow[tid      ] = __float2half((v0 - mu) * rstd * gam[tid      ] + bet[tid      ]);
    orow[tid + 128] = __float2half((v1 - mu) * rstd * gam[tid + 128] + bet[tid + 128]);
    orow[tid + 256] = __float2half((v2 - mu) * rstd * gam[tid + 256] + bet[tid + 256]);
}

// ---------------------------------------------------------------------------
// kernel_launch
// ---------------------------------------------------------------------------
extern "C" void kernel_launch(void* const* d_in, const int* in_sizes, int n_in,
                              void* d_out, int out_size)
{
    const float* x      = (const float*)d_in[0];
    const float* qkv_w  = (const float*)d_in[1];
    const float* proj_w = (const float*)d_in[2];
    const float* proj_b = (const float*)d_in[3];
    const float* n1_g   = (const float*)d_in[4];
    const float* n1_b   = (const float*)d_in[5];
    const float* n2_g   = (const float*)d_in[6];
    const float* n2_b   = (const float*)d_in[7];
    const float* fc1_w  = (const float*)d_in[8];
    const float* fc1_b  = (const float*)d_in[9];
    const float* fc2_w  = (const float*)d_in[10];
    const float* fc2_b  = (const float*)d_in[11];
    float* out = (float*)d_out;

    __half *xn, *qkv, *att, *x2, *h, *wq, *wp, *w1, *w2;
    float *xpT, *xpb;
    cudaGetSymbolAddress((void**)&xn,  g_xn);
    cudaGetSymbolAddress((void**)&xpT, g_xpT);
    cudaGetSymbolAddress((void**)&qkv, g_qkv);
    cudaGetSymbolAddress((void**)&att, g_att);
    cudaGetSymbolAddress((void**)&xpb, g_xpb);
    cudaGetSymbolAddress((void**)&x2,  g_x2);
    cudaGetSymbolAddress((void**)&h,   g_h);
    cudaGetSymbolAddress((void**)&wq,  g_wq);
    cudaGetSymbolAddress((void**)&wp,  g_wp);
    cudaGetSymbolAddress((void**)&w1,  g_w1);
    cudaGetSymbolAddress((void**)&w2,  g_w2);

    cudaFuncSetAttribute(gemm_f16_kernel,
                         cudaFuncAttributeMaxDynamicSharedMemorySize, GEMM_SMEM);
    cudaFuncSetAttribute(attn_kernel,
                         cudaFuncAttributeMaxDynamicSharedMemorySize, ATT_SMEM);

    // 0. convert all weights to half (single launch)
    convw4_kernel<<<(WNT + 255)/256, 256>>>(qkv_w, proj_w, fc1_w, fc2_w,
                                            wq, wp, w1, w2);

    // 1. LN1 + NCHW->NHWC transpose
    ln1_kernel<<<dim3(2, HH, BATCH), 256>>>(x, n1_g, n1_b, xn, xpT);

    // 2. QKV: [N,384] @ [1152,384]^T -> half
    gemm_f16_kernel<<<dim3(NTOK/128, QKVC/128), 256, GEMM_SMEM>>>(
        xn, wq, nullptr, nullptr, qkv, NTOK, QKVC, CCH, 0);

    // 3. row-strip attention + xn residual -> half
    attn_kernel<<<dim3(HH, 3, BATCH), 256, ATT_SMEM>>>(qkv, xn, att);

    // 4. proj + bias + residual(xpT) -> fp32 [N,C]
    gemm_f16_kernel<<<dim3(NTOK/128, CCH/128), 256, GEMM_SMEM>>>(
        att, wp, proj_b, xpT, xpb, NTOK, CCH, CCH, 2);

    // 5. LN2 -> half
    ln2_kernel<<<NTOK, 128>>>(xpb, n2_g, n2_b, x2);

    // 6. fc1 + bias + exact GELU -> half
    gemm_f16_kernel<<<dim3(NTOK/128, HIDN/128), 256, GEMM_SMEM>>>(
        x2, w1, fc1_b, nullptr, h, NTOK, HIDN, CCH, 1);

    // 7. fc2 + bias + residual(xpb) -> fp32 [B,C,HW] (fused transpose)
    gemm_f16_kernel<<<dim3(NTOK/128, CCH/128), 256, GEMM_SMEM>>>(
        h, w2, fc2_b, xpb, out, NTOK, CCH, HIDN, 3);
}

// round 17
// speedup vs baseline: 1.0903x; 1.0860x over previous
#include <cuda_runtime.h>
#include <cuda_fp16.h>
#include <math.h>
#include <stdint.h>

// ---------------------------------------------------------------------------
// Problem constants
// ---------------------------------------------------------------------------
#define BATCH 8
#define CCH   384
#define HH    56
#define WW    56
#define HWSZ  (HH*WW)         // 3136
#define NTOK  (BATCH*HWSZ)    // 25088
#define QKVC  (3*CCH)         // 1152
#define HIDN  1536
#define NHEAD 12
#define HDIM  32
#define EPSLN 1e-5f

// ---------------------------------------------------------------------------
// Scratch
// ---------------------------------------------------------------------------
__device__ __half g_xn [(size_t)NTOK*CCH];
__device__ float  g_xpT[(size_t)NTOK*CCH];
__device__ __half g_qkv[(size_t)NTOK*QKVC];
__device__ __half g_att[(size_t)NTOK*CCH];
__device__ float  g_xpb[(size_t)NTOK*CCH];
__device__ __half g_x2 [(size_t)NTOK*CCH];
__device__ __half g_h  [(size_t)NTOK*HIDN];
__device__ __half g_wq[(size_t)QKVC*CCH];
__device__ __half g_wp[(size_t)CCH*CCH];
__device__ __half g_w1[(size_t)HIDN*CCH];
__device__ __half g_w2[(size_t)CCH*HIDN];

// ---------------------------------------------------------------------------
// helpers
// ---------------------------------------------------------------------------
__device__ __forceinline__ uint32_t smem_u32(const void* p) {
    uint32_t a;
    asm("{ .reg .u64 t; cvta.to.shared.u64 t, %1; cvt.u32.u64 %0, t; }"
        : "=r"(a) : "l"(p));
    return a;
}
__device__ __forceinline__ void cp_async16(uint32_t s, const void* g) {
    asm volatile("cp.async.cg.shared.global [%0], [%1], 16;"
                 :: "r"(s), "l"(g));
}
__device__ __forceinline__ void cp_commit() {
    asm volatile("cp.async.commit_group;" ::: "memory");
}
template<int N>
__device__ __forceinline__ void cp_wait() {
    asm volatile("cp.async.wait_group %0;" :: "n"(N) : "memory");
}
__device__ __forceinline__ void ldmatrix_x4(uint32_t& r0, uint32_t& r1,
                                            uint32_t& r2, uint32_t& r3,
                                            uint32_t addr) {
    asm volatile("ldmatrix.sync.aligned.m8n8.x4.shared.b16 {%0,%1,%2,%3}, [%4];"
                 : "=r"(r0), "=r"(r1), "=r"(r2), "=r"(r3) : "r"(addr));
}
__device__ __forceinline__ void mma_f16(float* c, const uint32_t* a,
                                        const uint32_t* b) {
    asm volatile(
        "mma.sync.aligned.m16n8k16.row.col.f32.f16.f16.f32 "
        "{%0,%1,%2,%3}, {%4,%5,%6,%7}, {%8,%9}, {%0,%1,%2,%3};"
        : "+f"(c[0]), "+f"(c[1]), "+f"(c[2]), "+f"(c[3])
        : "r"(a[0]), "r"(a[1]), "r"(a[2]), "r"(a[3]),
          "r"(b[0]), "r"(b[1]));
}

// ---------------------------------------------------------------------------
// Fused weight convert fp32 -> half (all 4 weights in one launch)
// ---------------------------------------------------------------------------
#define WN1 (QKVC*CCH)
#define WN2 (CCH*CCH)
#define WN3 (HIDN*CCH)
#define WN4 (CCH*HIDN)
#define WNT (WN1+WN2+WN3+WN4)

__global__ __launch_bounds__(256) void convw4_kernel(
    const float* __restrict__ s1, const float* __restrict__ s2,
    const float* __restrict__ s3, const float* __restrict__ s4,
    __half* __restrict__ d1, __half* __restrict__ d2,
    __half* __restrict__ d3, __half* __restrict__ d4)
{
    int i = blockIdx.x * 256 + threadIdx.x;
    if (i < WN1) { d1[i] = __float2half(s1[i]); return; }
    i -= WN1;
    if (i < WN2) { d2[i] = __float2half(s2[i]); return; }
    i -= WN2;
    if (i < WN3) { d3[i] = __float2half(s3[i]); return; }
    i -= WN3;
    if (i < WN4) d4[i] = __float2half(s4[i]);
}

// ---------------------------------------------------------------------------
// fp16 mma.sync GEMM (round-12 best config):  C[M,Nc] = A[M,K] @ Bw[Nc,K]^T
// CTA tile 128x128, BK=64 halves (128B rows, XOR swizzle), 3-stage cp.async.
// 256 threads = 8 warps as 2(M)x4(N); warp tile 64x32 via m16n8k16 + ldmatrix.
// 2 CTAs/SM (96KB smem) -> 16 warps/SM.
// mode: 0 = plain -> half out
//       1 = bias + exact erf GELU -> half out
//       2 = bias + fp32 residual -> float out [N,C]
//       3 = bias + fp32 residual -> float out [B,C,HW] (fused transpose)
// ---------------------------------------------------------------------------
#define OPST   16384
#define NSTAGE 3
#define GEMM_SMEM (NSTAGE*2*OPST)    // 98304

__global__ __launch_bounds__(256, 2) void gemm_f16_kernel(
    const __half* __restrict__ A, const __half* __restrict__ Bw,
    const float* __restrict__ bias, const float* __restrict__ resid,
    void* __restrict__ Cout, int M, int Nc, int K, int mode)
{
    extern __shared__ char smem[];
    uint32_t sb = smem_u32(smem);

    int tid    = threadIdx.x;
    int wid    = tid >> 5;
    int lane   = tid & 31;
    int warp_m = wid & 1;
    int warp_n = wid >> 1;
    int m0     = blockIdx.x * 128;
    int n0     = blockIdx.y * 128;

    const __half* Ab = A  + (size_t)m0 * K;
    const __half* Bb = Bw + (size_t)n0 * K;
    const int NCH = K >> 6;

    int gid = lane >> 2;
    int tig = lane & 3;

    int arow_l = (lane & 7) + ((lane >> 3) & 1) * 8;
    int asub   = (lane >> 4) & 1;
    int brow_l = (lane & 7) + ((lane >> 4) & 1) * 8;
    int bsub   = (lane >> 3) & 1;

    float acc[4][4][4];
    #pragma unroll
    for (int i = 0; i < 4; i++)
        #pragma unroll
        for (int j = 0; j < 4; j++)
            #pragma unroll
            for (int q = 0; q < 4; q++) acc[i][j][q] = 0.f;

    auto load_chunk = [&](int kc, int st) {
        uint32_t abase = sb + st * (2*OPST);
        uint32_t bbase = abase + OPST;
        int kh = kc << 6;
        #pragma unroll
        for (int r = 0; r < 8; r++) {
            int idx = tid + r * 256;
            int op  = idx >> 10;
            int wi  = idx & 1023;
            int row = wi >> 3;
            int g   = wi & 7;
            uint32_t dst = (op ? bbase : abase)
                         + (uint32_t)(row * 128 + ((g ^ (row & 7)) << 4));
            const __half* src = (op ? Bb : Ab) + (size_t)row * K + kh + g * 8;
            cp_async16(dst, src);
        }
        cp_commit();
    };

    load_chunk(0, 0);
    load_chunk(1, 1);

    for (int i = 0; i < NCH; i++) {
        if (i < NCH - 1) cp_wait<1>(); else cp_wait<0>();
        __syncthreads();

        int st = i % NSTAGE;
        uint32_t abase = sb + st * (2*OPST);
        uint32_t bbase = abase + OPST;

        #pragma unroll
        for (int ks = 0; ks < 4; ks++) {
            uint32_t afr[4][4];
            #pragma unroll
            for (int mf = 0; mf < 4; mf++) {
                int row = warp_m * 64 + mf * 16 + arow_l;
                int gph = ((ks * 2 + asub) ^ (row & 7));
                ldmatrix_x4(afr[mf][0], afr[mf][1], afr[mf][2], afr[mf][3],
                            abase + (uint32_t)(row * 128 + gph * 16));
            }
            uint32_t bfr[4][2];
            #pragma unroll
            for (int pf = 0; pf < 2; pf++) {
                int row = warp_n * 32 + pf * 16 + brow_l;
                int gph = ((ks * 2 + bsub) ^ (row & 7));
                ldmatrix_x4(bfr[2*pf][0], bfr[2*pf][1],
                            bfr[2*pf+1][0], bfr[2*pf+1][1],
                            bbase + (uint32_t)(row * 128 + gph * 16));
            }
            #pragma unroll
            for (int mf = 0; mf < 4; mf++)
                #pragma unroll
                for (int nf = 0; nf < 4; nf++)
                    mma_f16(acc[mf][nf], afr[mf], bfr[nf]);
        }

        if (i + 2 < NCH) load_chunk(i + 2, (i + 2) % NSTAGE);
    }

    // ---------------- epilogue ----------------
    if (mode == 3) {
        __syncthreads();
        float* tile = (float*)smem;            // [128][129]
        #pragma unroll
        for (int mf = 0; mf < 4; mf++) {
            #pragma unroll
            for (int nf = 0; nf < 4; nf++) {
                int rl = warp_m * 64 + mf * 16 + gid;
                int cl = warp_n * 32 + nf * 8 + tig * 2;
                #pragma unroll
                for (int half_i = 0; half_i < 2; half_i++) {
                    int r = rl + half_i * 8;
                    size_t rr = (size_t)(m0 + r);
                    float v0 = acc[mf][nf][half_i * 2 + 0] + bias[n0 + cl];
                    float v1 = acc[mf][nf][half_i * 2 + 1] + bias[n0 + cl + 1];
                    float2 rv = *(const float2*)&resid[rr * Nc + n0 + cl];
                    v0 += rv.x; v1 += rv.y;
                    tile[r * 129 + cl    ] = v0;
                    tile[r * 129 + cl + 1] = v1;
                }
            }
        }
        __syncthreads();
        float* out = (float*)Cout;
        #pragma unroll
        for (int cs = 0; cs < 16; cs++) {
            int c = wid * 16 + cs;
            #pragma unroll
            for (int rs = 0; rs < 4; rs++) {
                int r  = rs * 32 + lane;
                int rr = m0 + r;
                int b  = rr / HWSZ;
                int s  = rr - b * HWSZ;
                out[((size_t)b * CCH + n0 + c) * HWSZ + s] = tile[r * 129 + c];
            }
        }
        return;
    }

    #pragma unroll
    for (int mf = 0; mf < 4; mf++) {
        #pragma unroll
        for (int nf = 0; nf < 4; nf++) {
            int row = m0 + warp_m * 64 + mf * 16 + gid;
            int col = n0 + warp_n * 32 + nf * 8 + tig * 2;
            #pragma unroll
            for (int half_i = 0; half_i < 2; half_i++) {
                size_t rr = (size_t)(row + half_i * 8);
                float v0 = acc[mf][nf][half_i * 2 + 0];
                float v1 = acc[mf][nf][half_i * 2 + 1];
                if (bias) { v0 += bias[col]; v1 += bias[col + 1]; }
                if (mode == 1) {
                    v0 = 0.5f * v0 * (1.0f + erff(v0 * 0.7071067811865476f));
                    v1 = 0.5f * v1 * (1.0f + erff(v1 * 0.7071067811865476f));
                }
                if (mode == 2) {
                    float2 rv = *(const float2*)&resid[rr * Nc + col];
                    v0 += rv.x; v1 += rv.y;
                    float2 o; o.x = v0; o.y = v1;
                    *(float2*)&((float*)Cout)[rr * Nc + col] = o;
                } else {
                    __half2 o = __floats2half2_rn(v0, v1);
                    *(__half2*)&((__half*)Cout)[rr * Nc + col] = o;
                }
            }
        }
    }
}

// ---------------------------------------------------------------------------
// LN1: x [B,C,H,W] -> xn [N,C] (half) + xpT [N,C] (fp32)
// ---------------------------------------------------------------------------
__global__ __launch_bounds__(256) void ln1_kernel(
    const float* __restrict__ x, const float* __restrict__ gam,
    const float* __restrict__ bet, __half* __restrict__ xn,
    float* __restrict__ xpT)
{
    const int TPB = 28;
    __shared__ float s[CCH*TPB];
    __shared__ float ps[9*TPB];
    __shared__ float pq[9*TPB];
    __shared__ float s_mean[TPB];
    __shared__ float s_rstd[TPB];

    int tid = threadIdx.x;
    int x0  = blockIdx.x * TPB;
    int y   = blockIdx.y;
    int b   = blockIdx.z;

    for (int idx = tid; idx < CCH*TPB; idx += 256) {
        int c = idx / TPB;
        int t = idx % TPB;
        s[idx] = x[(((size_t)b*CCH + c)*HH + y)*WW + x0 + t];
    }
    __syncthreads();

    if (tid < 9*TPB) {
        int sub = tid / TPB;
        int t   = tid % TPB;
        float sm = 0.f, sq = 0.f;
        for (int c = sub; c < CCH; c += 9) {
            float v = s[c*TPB + t];
            sm += v; sq += v*v;
        }
        ps[sub*TPB + t] = sm;
        pq[sub*TPB + t] = sq;
    }
    __syncthreads();
    if (tid < TPB) {
        float sm = 0.f, sq = 0.f;
        #pragma unroll
        for (int sub = 0; sub < 9; sub++) { sm += ps[sub*TPB + tid]; sq += pq[sub*TPB + tid]; }
        float mu  = sm * (1.f/CCH);
        float var = sq * (1.f/CCH) - mu*mu;
        s_mean[tid] = mu;
        s_rstd[tid] = rsqrtf(var + EPSLN);
    }
    __syncthreads();

    for (int idx = tid; idx < CCH*TPB; idx += 256) {
        int t = idx / CCH;
        int c = idx % CCH;
        float v = s[c*TPB + t];
        size_t n = (size_t)b*HWSZ + (size_t)y*WW + (x0 + t);
        xpT[n*CCH + c] = v;
        xn [n*CCH + c] =
            __float2half((v - s_mean[t]) * s_rstd[t] * gam[c] + bet[c]);
    }
}

// ---------------------------------------------------------------------------
// Multi-dilation 3x3 local attention + fused "+xn" residual.
// One warp = one head x EIGHT adjacent tokens (8p..8p+7 along W; WW%8==0 so
// groups never cross rows). 4 lanes per token, 8 dims (int4 = 4 x half2) per
// lane. Butterfly offsets 2,1 within each 4-lane group. 32-bit addressing;
// neighbor deltas warp-uniform. OOB -> logit 0, v 0 (zero-pad unfold).
// ---------------------------------------------------------------------------
__global__ __launch_bounds__(384) void attn_kernel(
    const __half* __restrict__ qkv, const __half* __restrict__ xn,
    __half* __restrict__ att)
{
    int n    = blockIdx.x * 8 + ((threadIdx.x >> 2) & 7);
    int w    = threadIdx.x >> 5;      // head 0..11
    int l4   = threadIdx.x & 3;       // 8-dim group index

    int b    = n / HWSZ;
    int rem  = n - b * HWSZ;
    int y    = rem / WW;
    int xx   = rem - y * WW;

    int dil  = (w >> 2) + 1;          // DILS = (1,2,3)
    int c0   = w * HDIM;

    const float scale = 0.17677669529663687f;   // 32^-0.5

    uint32_t base = (uint32_t)n * QKVC + c0 + 8 * l4;

    int4 qi = *(const int4*)(qkv + base);
    const __half2* qh = (const __half2*)&qi;
    float2 qf[4];
    #pragma unroll
    for (int j = 0; j < 4; j++) qf[j] = __half22float2(qh[j]);

    float    logit[9];
    int      delta[9];
    unsigned okm = 0;
    #pragma unroll
    for (int e = 0; e < 9; e++) {
        int ki = e / 3, kj = e % 3;
        int ny = y  + (ki - 1) * dil;
        int nx = xx + (kj - 1) * dil;
        bool ok = ((unsigned)ny < HH) && ((unsigned)nx < WW);
        delta[e] = ((ki - 1) * WW + (kj - 1)) * dil * QKVC;
        float p = 0.f;
        if (ok) {
            okm |= (1u << e);
            int4 kv = *(const int4*)(qkv + (int)base + CCH + delta[e]);
            const __half2* kh = (const __half2*)&kv;
            #pragma unroll
            for (int j = 0; j < 4; j++) {
                float2 kf = __half22float2(kh[j]);
                p = fmaf(qf[j].x, kf.x, p);
                p = fmaf(qf[j].y, kf.y, p);
            }
        }
        p += __shfl_xor_sync(0xffffffffu, p, 2);
        p += __shfl_xor_sync(0xffffffffu, p, 1);
        logit[e] = p * scale;
    }

    float mx = logit[0];
    #pragma unroll
    for (int e = 1; e < 9; e++) mx = fmaxf(mx, logit[e]);
    float pe[9];
    float sum = 0.f;
    #pragma unroll
    for (int e = 0; e < 9; e++) { pe[e] = __expf(logit[e] - mx); sum += pe[e]; }
    float inv = 1.f / sum;

    float ox[8];
    #pragma unroll
    for (int j = 0; j < 8; j++) ox[j] = 0.f;
    #pragma unroll
    for (int e = 0; e < 9; e++) {
        if (okm & (1u << e)) {
            int4 vv = *(const int4*)(qkv + (int)base + 2*CCH + delta[e]);
            const __half2* vh = (const __half2*)&vv;
            float p = pe[e] * inv;
            #pragma unroll
            for (int j = 0; j < 4; j++) {
                float2 vf = __half22float2(vh[j]);
                ox[2*j  ] = fmaf(p, vf.x, ox[2*j  ]);
                ox[2*j+1] = fmaf(p, vf.y, ox[2*j+1]);
            }
        }
    }

    uint32_t obase = (uint32_t)n * CCH + c0 + 8 * l4;
    int4 xi = *(const int4*)(xn + obase);
    const __half2* xh = (const __half2*)&xi;
    int4 oi;
    __half2* oh = (__half2*)&oi;
    #pragma unroll
    for (int j = 0; j < 4; j++) {
        float2 xf = __half22float2(xh[j]);
        oh[j] = __floats2half2_rn(ox[2*j] + xf.x, ox[2*j+1] + xf.y);
    }
    *(int4*)(att + obase) = oi;
}

// ---------------------------------------------------------------------------
// LN2: fp32 in -> half out
// ---------------------------------------------------------------------------
__global__ __launch_bounds__(128) void ln2_kernel(
    const float* __restrict__ in, const float* __restrict__ gam,
    const float* __restrict__ bet, __half* __restrict__ out)
{
    __shared__ float rs[4], rq[4];
    __shared__ float s_mu, s_rstd;
    int n   = blockIdx.x;
    int tid = threadIdx.x;
    const float* row = in + (size_t)n * CCH;

    float v0 = row[tid];
    float v1 = row[tid + 128];
    float v2 = row[tid + 256];
    float sm = v0 + v1 + v2;
    float sq = v0*v0 + v1*v1 + v2*v2;
    #pragma unroll
    for (int off = 16; off > 0; off >>= 1) {
        sm += __shfl_xor_sync(0xffffffffu, sm, off);
        sq += __shfl_xor_sync(0xffffffffu, sq, off);
    }
    int wid = tid >> 5, lane = tid & 31;
    if (lane == 0) { rs[wid] = sm; rq[wid] = sq; }
    __syncthreads();
    if (tid == 0) {
        float tsm = rs[0]+rs[1]+rs[2]+rs[3];
        float tsq = rq[0]+rq[1]+rq[2]+rq[3];
        float mu  = tsm * (1.f/CCH);
        float var = tsq * (1.f/CCH) - mu*mu;
        s_mu = mu;
        s_rstd = rsqrtf(var + EPSLN);
    }
    __syncthreads();
    float mu = s_mu, rstd = s_rstd;
    __half* orow = out + (size_t)n * CCH;
    orow[tid      ] = __float2half((v0 - mu) * rstd * gam[tid      ] + bet[tid      ]);
    orow[tid + 128] = __float2half((v1 - mu) * rstd * gam[tid + 128] + bet[tid + 128]);
    orow[tid + 256] = __float2half((v2 - mu) * rstd * gam[tid + 256] + bet[tid + 256]);
}

// ---------------------------------------------------------------------------
// kernel_launch
// ---------------------------------------------------------------------------
extern "C" void kernel_launch(void* const* d_in, const int* in_sizes, int n_in,
                              void* d_out, int out_size)
{
    const float* x      = (const float*)d_in[0];
    const float* qkv_w  = (const float*)d_in[1];
    const float* proj_w = (const float*)d_in[2];
    const float* proj_b = (const float*)d_in[3];
    const float* n1_g   = (const float*)d_in[4];
    const float* n1_b   = (const float*)d_in[5];
    const float* n2_g   = (const float*)d_in[6];
    const float* n2_b   = (const float*)d_in[7];
    const float* fc1_w  = (const float*)d_in[8];
    const float* fc1_b  = (const float*)d_in[9];
    const float* fc2_w  = (const float*)d_in[10];
    const float* fc2_b  = (const float*)d_in[11];
    float* out = (float*)d_out;

    __half *xn, *qkv, *att, *x2, *h, *wq, *wp, *w1, *w2;
    float *xpT, *xpb;
    cudaGetSymbolAddress((void**)&xn,  g_xn);
    cudaGetSymbolAddress((void**)&xpT, g_xpT);
    cudaGetSymbolAddress((void**)&qkv, g_qkv);
    cudaGetSymbolAddress((void**)&att, g_att);
    cudaGetSymbolAddress((void**)&xpb, g_xpb);
    cudaGetSymbolAddress((void**)&x2,  g_x2);
    cudaGetSymbolAddress((void**)&h,   g_h);
    cudaGetSymbolAddress((void**)&wq,  g_wq);
    cudaGetSymbolAddress((void**)&wp,  g_wp);
    cudaGetSymbolAddress((void**)&w1,  g_w1);
    cudaGetSymbolAddress((void**)&w2,  g_w2);

    cudaFuncSetAttribute(gemm_f16_kernel,
                         cudaFuncAttributeMaxDynamicSharedMemorySize, GEMM_SMEM);

    // 0. convert all weights to half (single launch)
    convw4_kernel<<<(WNT + 255)/256, 256>>>(qkv_w, proj_w, fc1_w, fc2_w,
                                            wq, wp, w1, w2);

    // 1. LN1 + NCHW->NHWC transpose
    ln1_kernel<<<dim3(2, HH, BATCH), 256>>>(x, n1_g, n1_b, xn, xpT);

    // 2. QKV: [N,384] @ [1152,384]^T -> half
    gemm_f16_kernel<<<dim3(NTOK/128, QKVC/128), 256, GEMM_SMEM>>>(
        xn, wq, nullptr, nullptr, qkv, NTOK, QKVC, CCH, 0);

    // 3. attention + xn residual -> half (8 tokens per warp)
    attn_kernel<<<NTOK/8, 384>>>(qkv, xn, att);

    // 4. proj + bias + residual(xpT) -> fp32 [N,C]
    gemm_f16_kernel<<<dim3(NTOK/128, CCH/128), 256, GEMM_SMEM>>>(
        att, wp, proj_b, xpT, xpb, NTOK, CCH, CCH, 2);

    // 5. LN2 -> half
    ln2_kernel<<<NTOK, 128>>>(xpb, n2_g, n2_b, x2);

    // 6. fc1 + bias + exact GELU -> half
    gemm_f16_kernel<<<dim3(NTOK/128, HIDN/128), 256, GEMM_SMEM>>>(
        x2, w1, fc1_b, nullptr, h, NTOK, HIDN, CCH, 1);

    // 7. fc2 + bias + residual(xpb) -> fp32 [B,C,HW] (fused transpose)
    gemm_f16_kernel<<<dim3(NTOK/128, CCH/128), 256, GEMM_SMEM>>>(
        h, w2, fc2_b, xpb, out, NTOK, CCH, HIDN, 3);
}